// round 14
// baseline (speedup 1.0000x reference)
#include <cuda_runtime.h>
#include <cuda_bf16.h>
#include <math.h>
#include <stdint.h>

// ---------------------------------------------------------------------------
// Problem constants
// ---------------------------------------------------------------------------
constexpr int T_TOK = 4096;
constexpr int HDIM  = 2048;
constexpr int FMOE  = 1024;
constexpr int FSH   = 2048;
constexpr int NEXP  = 16;
constexpr int TOPK  = 4;
constexpr int NGRP  = 4;
constexpr int EPG   = NEXP / NGRP;
constexpr int NASS  = T_TOK * TOPK;
constexpr float RSCALE = 2.5f;

// ---------------------------------------------------------------------------
// Scratch layout (identical to R6/R12/R13)
// ---------------------------------------------------------------------------
constexpr size_t SZ_RW  = (size_t)NEXP * FMOE * HDIM * 2;
constexpr size_t SZ_DW  = (size_t)NEXP * HDIM * FMOE * 2;
constexpr size_t SZ_SW  = (size_t)FSH * HDIM * 2;
constexpr size_t SZ_HID = (size_t)T_TOK * HDIM * 2;
constexpr size_t SZ_GU  = (size_t)NASS * FMOE * 4;
constexpr size_t SZ_ACT = (size_t)NASS * FMOE * 2;
constexpr size_t SZ_SHB = (size_t)T_TOK * FSH * 4;
constexpr size_t SZ_SHA = (size_t)T_TOK * FSH * 2;
constexpr size_t SZ_PART= (size_t)NASS * HDIM * 4;

constexpr size_t O_WG_HI  = 0;
constexpr size_t O_WG_LO  = O_WG_HI  + SZ_RW;
constexpr size_t O_WU_HI  = O_WG_LO  + SZ_RW;
constexpr size_t O_WU_LO  = O_WU_HI  + SZ_RW;
constexpr size_t O_WD_HI  = O_WU_LO  + SZ_RW;
constexpr size_t O_WD_LO  = O_WD_HI  + SZ_DW;
constexpr size_t O_WSG_HI = O_WD_LO  + SZ_DW;
constexpr size_t O_WSG_LO = O_WSG_HI + SZ_SW;
constexpr size_t O_WSU_HI = O_WSG_LO + SZ_SW;
constexpr size_t O_WSU_LO = O_WSU_HI + SZ_SW;
constexpr size_t O_WSD_HI = O_WSU_LO + SZ_SW;
constexpr size_t O_WSD_LO = O_WSD_HI + SZ_SW;
constexpr size_t O_HID_HI = O_WSD_LO + SZ_SW;
constexpr size_t O_HID_LO = O_HID_HI + SZ_HID;
constexpr size_t O_GBUF   = O_HID_LO + SZ_HID;
constexpr size_t O_UBUF   = O_GBUF   + SZ_GU;
constexpr size_t O_ACT_HI = O_UBUF   + SZ_GU;
constexpr size_t O_ACT_LO = O_ACT_HI + SZ_ACT;
constexpr size_t O_SHG    = O_ACT_LO + SZ_ACT;
constexpr size_t O_SHU    = O_SHG    + SZ_SHB;
constexpr size_t O_SHA_HI = O_SHU    + SZ_SHB;
constexpr size_t O_SHA_LO = O_SHA_HI + SZ_SHA;
constexpr size_t O_PART   = O_SHA_LO + SZ_SHA;
constexpr size_t O_TOTAL  = O_PART   + SZ_PART;

__device__ __align__(256) char g_scratch[O_TOTAL];

__device__ int   g_counts[NEXP];
__device__ int   g_fill[NEXP];
__device__ int   g_offsets[NEXP + 1];
__device__ int   g_topk_idx[NASS];
__device__ float g_topk_w[NASS];
__device__ int   g_tk[NASS];
__device__ float g_w[NASS];

// ---------------------------------------------------------------------------
// Helpers
// ---------------------------------------------------------------------------
__device__ __forceinline__ uint32_t smem_to_u32(const void* p) {
    uint32_t a;
    asm("{ .reg .u64 t; cvta.to.shared.u64 t, %1; cvt.u32.u64 %0, t; }"
        : "=r"(a) : "l"(p));
    return a;
}
__device__ __forceinline__ uint32_t swz32(uint32_t x) {
    return x ^ ((x >> 3) & 0x70u);
}
__device__ __forceinline__ float silu(float x) { return x / (1.f + expf(-x)); }

__device__ __forceinline__ void cp16(uint32_t dst, const void* src) {
    asm volatile("cp.async.cg.shared.global [%0], [%1], 16;" :: "r"(dst), "l"(src));
}
__device__ __forceinline__ void ldsm_x4(uint32_t* r, uint32_t addr) {
    asm volatile("ldmatrix.sync.aligned.m8n8.x4.shared.b16 {%0,%1,%2,%3}, [%4];"
        : "=r"(r[0]), "=r"(r[1]), "=r"(r[2]), "=r"(r[3]) : "r"(addr));
}
__device__ __forceinline__ void mma_bf16(float* c, const uint32_t* a, const uint32_t* b) {
    asm volatile(
        "mma.sync.aligned.m16n8k16.row.col.f32.bf16.bf16.f32 "
        "{%0,%1,%2,%3}, {%4,%5,%6,%7}, {%8,%9}, {%0,%1,%2,%3};"
        : "+f"(c[0]), "+f"(c[1]), "+f"(c[2]), "+f"(c[3])
        : "r"(a[0]), "r"(a[1]), "r"(a[2]), "r"(a[3]), "r"(b[0]), "r"(b[1]));
}

// ---------------------------------------------------------------------------
// zero counters
// ---------------------------------------------------------------------------
__global__ void zero_kernel() {
    int i = threadIdx.x;
    if (i < NEXP) { g_counts[i] = 0; g_fill[i] = 0; }
}

// ---------------------------------------------------------------------------
// Router (validated R4/R6)
// ---------------------------------------------------------------------------
__global__ void router_kernel(const float* __restrict__ hidden,
                              const float* __restrict__ gw,
                              const float* __restrict__ bias) {
    int t    = blockIdx.x;
    int lane = threadIdx.x & 31;
    int wid  = threadIdx.x >> 5;
    __shared__ float slog[NEXP];

    const float* hrow = hidden + (size_t)t * HDIM;
    const float* wrow = gw + (size_t)wid * HDIM;
    float s = 0.f;
    for (int h = lane; h < HDIM; h += 32) s += hrow[h] * wrow[h];
#pragma unroll
    for (int o = 16; o > 0; o >>= 1) s += __shfl_down_sync(0xffffffffu, s, o);
    if (lane == 0) slog[wid] = s;
    __syncthreads();

    if (threadIdx.x == 0) {
        float sc[NEXP], s4c[NEXP];
#pragma unroll
        for (int e = 0; e < NEXP; e++) {
            float sg = 1.f / (1.f + expf(-slog[e]));
            sc[e] = sg; s4c[e] = sg + bias[e];
        }
        float gsc[NGRP];
#pragma unroll
        for (int g = 0; g < NGRP; g++) {
            int i1 = 0; float v1 = -INFINITY;
            for (int j = 0; j < EPG; j++) {
                float v = s4c[g * EPG + j];
                if (v > v1) { v1 = v; i1 = j; }
            }
            float v2 = -INFINITY;
            for (int j = 0; j < EPG; j++) {
                if (j == i1) continue;
                float v = s4c[g * EPG + j];
                if (v > v2) v2 = v;
            }
            gsc[g] = v1 + v2;
        }
        int g0 = 0; float gv0 = -INFINITY;
        for (int g = 0; g < NGRP; g++) if (gsc[g] > gv0) { gv0 = gsc[g]; g0 = g; }
        int g1 = -1; float gv1 = -INFINITY;
        for (int g = 0; g < NGRP; g++) {
            if (g == g0) continue;
            if (gsc[g] > gv1) { gv1 = gsc[g]; g1 = g; }
        }
        float masked[NEXP];
#pragma unroll
        for (int e = 0; e < NEXP; e++) {
            int g = e / EPG;
            masked[e] = (g == g0 || g == g1) ? s4c[e] : -INFINITY;
        }
        int idx[TOPK]; float wraw[TOPK]; float wsum = 0.f;
#pragma unroll
        for (int k = 0; k < TOPK; k++) {
            int best = 0; float bv = -INFINITY;
            for (int e = 0; e < NEXP; e++)
                if (masked[e] > bv) { bv = masked[e]; best = e; }
            masked[best] = -INFINITY;
            idx[k] = best; wraw[k] = sc[best]; wsum += sc[best];
        }
        float inv = RSCALE / (wsum + 1e-20f);
#pragma unroll
        for (int k = 0; k < TOPK; k++) {
            g_topk_idx[t * TOPK + k] = idx[k];
            g_topk_w[t * TOPK + k]   = wraw[k] * inv;
            atomicAdd(&g_counts[idx[k]], 1);
        }
    }
}

__global__ void offsets_kernel() {
    if (threadIdx.x == 0) {
        int acc = 0;
        for (int e = 0; e < NEXP; e++) { g_offsets[e] = acc; acc += g_counts[e]; }
        g_offsets[NEXP] = acc;
    }
}

__global__ void dispatch_kernel() {
    int t = blockIdx.x * blockDim.x + threadIdx.x;
    if (t >= T_TOK) return;
#pragma unroll
    for (int k = 0; k < TOPK; k++) {
        int e    = g_topk_idx[t * TOPK + k];
        int pos  = atomicAdd(&g_fill[e], 1);
        int slot = g_offsets[e] + pos;
        g_tk[slot] = t * TOPK + k;
        g_w[slot]  = g_topk_w[t * TOPK + k];
    }
}

// ---------------------------------------------------------------------------
// split helpers: x = hi(bf16) + lo(bf16)
// ---------------------------------------------------------------------------
__device__ __forceinline__ void split_pair(float a0, float a1,
                                           __nv_bfloat162& hp, __nv_bfloat162& lp) {
    hp = __floats2bfloat162_rn(a0, a1);
    float l0 = a0 - __bfloat162float(__low2bfloat16(hp));
    float l1 = a1 - __bfloat162float(__high2bfloat16(hp));
    lp = __floats2bfloat162_rn(l0, l1);
}

// ---------------------------------------------------------------------------
// prep kernels (exactly as R6/R12/R13)
// ---------------------------------------------------------------------------
template <int F, int K>
__global__ void prep_weight(const float* __restrict__ src,
                            size_t hi_off, size_t lo_off, int npairs) {
    int i = blockIdx.x * blockDim.x + threadIdx.x;
    if (i >= npairs) return;
    size_t elem = (size_t)i * 2;
    int k = (int)(elem % K);
    int f = (int)((elem / K) % F);
    int e = (int)(elem / ((size_t)K * F));
    float2 v = *(const float2*)(src + elem);
    __nv_bfloat162 hp, lp;
    split_pair(v.x, v.y, hp, lp);
    int n = f >> 7, r = f & 127, c = k >> 6, col = k & 63;
    size_t tb = ((size_t)(e * (F >> 7) + n) * (K >> 6) + c) * 16384;
    int off = r * 128 + col * 2;
    int sw = off ^ ((off >> 3) & 0x70);
    *(__nv_bfloat162*)(g_scratch + hi_off + tb + sw) = hp;
    *(__nv_bfloat162*)(g_scratch + lo_off + tb + sw) = lp;
}

__global__ void prep_split(const float* __restrict__ src,
                           size_t hi_off, size_t lo_off, int npairs) {
    int i = blockIdx.x * blockDim.x + threadIdx.x;
    if (i >= npairs) return;
    float2 v = *(const float2*)(src + (size_t)i * 2);
    __nv_bfloat162 hp, lp;
    split_pair(v.x, v.y, hp, lp);
    ((__nv_bfloat162*)(g_scratch + hi_off))[i] = hp;
    ((__nv_bfloat162*)(g_scratch + lo_off))[i] = lp;
}

__global__ void act_kernel(size_t g_off, size_t u_off,
                           size_t hi_off, size_t lo_off, int npairs) {
    int i = blockIdx.x * blockDim.x + threadIdx.x;
    if (i >= npairs) return;
    float2 g2 = ((const float2*)(g_scratch + g_off))[i];
    float2 u2 = ((const float2*)(g_scratch + u_off))[i];
    float a0 = silu(g2.x) * u2.x;
    float a1 = silu(g2.y) * u2.y;
    __nv_bfloat162 hp, lp;
    split_pair(a0, a1, hp, lp);
    ((__nv_bfloat162*)(g_scratch + hi_off))[i] = hp;
    ((__nv_bfloat162*)(g_scratch + lo_off))[i] = lp;
}

// ---------------------------------------------------------------------------
// Grouped GEMM — 512 threads (occ 25%, measured win R13), CTA tile 256x128,
// warp tile 64x32 (4 m-warps x 4 n-warps) for 4 MMA/ldsm (L1 relief).
// K chunk 64, 2-stage cp.async (96KB/stage), fragment-major split-bf16 3-term.
// AMODE: 0 plain rows, 1 gather hidden rows via g_tk, 2 slot rows.
// EMODE: 0 plain store, 1 scale by g_w + scatter to g_part[tk].
// Stage layout: Ah[0,32K) Al[32K,64K) Bh[64K,80K) Bl[80K,96K).
// ---------------------------------------------------------------------------
constexpr int STAGE_BYTES = 98304;
constexpr int GSMEM_BYTES = 2 * STAGE_BYTES;   // 192 KB
constexpr int GT = 512;

template <int KD, int ND, int AMODE, int EMODE>
__global__ void __launch_bounds__(GT)
mma_gemm(size_t a_hi_off, size_t a_lo_off,
         size_t w_hi_off, size_t w_lo_off,
         size_t out_off, float* ext_out) {
    constexpr int KC = KD / 64;
    constexpr int NT = ND / 128;
    extern __shared__ char smem[];
    uint32_t sb = smem_to_u32(smem);

    int e, seg, nrows;
    if (AMODE == 0) { e = 0; seg = 0; nrows = T_TOK; }
    else { e = blockIdx.z; seg = g_offsets[e]; nrows = g_offsets[e + 1] - seg; }
    int m0 = blockIdx.y * 256;
    if (m0 >= nrows) return;
    int nb = blockIdx.x;

    int tid = threadIdx.x, wid = tid >> 5, lid = tid & 31;

    // ---- A staging: thread = (row r=tid>>1 of 256, half of 128B row) ----
    const __nv_bfloat16* a_hi = (const __nv_bfloat16*)(g_scratch + a_hi_off);
    const __nv_bfloat16* a_lo = (const __nv_bfloat16*)(g_scratch + a_lo_off);
    int r = tid >> 1, half = tid & 1;
    int mrow = m0 + r;
    bool av = mrow < nrows;
    size_t arow;
    if (AMODE == 1)      arow = (size_t)(g_tk[seg + (av ? mrow : m0)] >> 2);
    else if (AMODE == 2) arow = (size_t)(seg + (av ? mrow : m0));
    else                 arow = (size_t)(av ? mrow : m0);
    const char* ah0 = (const char*)(a_hi + arow * KD + half * 32);
    const char* al0 = (const char*)(a_lo + arow * KD + half * 32);
    uint32_t asw[4];
#pragma unroll
    for (int u = 0; u < 4; u++)
        asw[u] = swz32((uint32_t)(r * 128 + half * 64 + u * 16));

    // ---- B: preswizzled 16KB tiles, identity copy; 2x16B per image ----
    size_t wtile = (size_t)(e * NT + nb) * KC;
    const char* bh0 = g_scratch + w_hi_off + wtile * 16384 + tid * 32;
    const char* bl0 = g_scratch + w_lo_off + wtile * 16384 + tid * 32;

    // warp layout: 4 m-warps x 4 n-warps, warp tile 64x32
    int wm = (wid & 3) * 64, wn = (wid >> 2) * 32;
    float acc[4][4][4];
#pragma unroll
    for (int a = 0; a < 4; a++)
#pragma unroll
        for (int b = 0; b < 4; b++)
#pragma unroll
            for (int c2 = 0; c2 < 4; c2++) acc[a][b][c2] = 0.f;

    auto stage = [&](int c) {
        uint32_t X = sb + (uint32_t)(c & 1) * (uint32_t)STAGE_BYTES;
        const char* ah = ah0 + (size_t)c * 128;
        const char* al = al0 + (size_t)c * 128;
        const char* bh = bh0 + (size_t)c * 16384;
        const char* bl = bl0 + (size_t)c * 16384;
#pragma unroll
        for (int u = 0; u < 4; u++) {
            cp16(X + asw[u],         ah + u * 16);
            cp16(X + 32768 + asw[u], al + u * 16);
        }
#pragma unroll
        for (int u = 0; u < 2; u++) {
            cp16(X + 65536 + tid * 32 + u * 16, bh + u * 16);
            cp16(X + 81920 + tid * 32 + u * 16, bl + u * 16);
        }
        asm volatile("cp.async.commit_group;");
    };

    auto compute = [&](int s) {
        uint32_t X = sb + (uint32_t)s * (uint32_t)STAGE_BYTES;
        int g = lid >> 3;
#pragma unroll
        for (int k16 = 0; k16 < 4; k16++) {
            int kb = k16 * 32;
            // B fragments once per k16 (shared across all 4 mf)
            uint32_t bfh[4][2], bfl[4][2];
#pragma unroll
            for (int nq = 0; nq < 2; nq++) {
                int rr = wn + nq * 16 + (lid & 7) + (g >> 1) * 8;
                int bb = kb + (g & 1) * 16;
                uint32_t ad = X + 65536 + swz32((uint32_t)(rr * 128 + bb));
                uint32_t t4[4];
                ldsm_x4(t4, ad);
                bfh[2*nq][0] = t4[0]; bfh[2*nq][1] = t4[1];
                bfh[2*nq+1][0] = t4[2]; bfh[2*nq+1][1] = t4[3];
                ldsm_x4(t4, ad + 16384);
                bfl[2*nq][0] = t4[0]; bfl[2*nq][1] = t4[1];
                bfl[2*nq+1][0] = t4[2]; bfl[2*nq+1][1] = t4[3];
            }
            // A fragments per mf; fragment-major 3-term (R6 ordering)
#pragma unroll
            for (int mf = 0; mf < 4; mf++) {
                int rr = wm + mf * 16 + (lid & 7) + (g & 1) * 8;
                int bb = kb + (g >> 1) * 16;
                uint32_t ad = X + swz32((uint32_t)(rr * 128 + bb));
                uint32_t afh[4], afl[4];
                ldsm_x4(afh, ad);
                ldsm_x4(afl, ad + 32768);
#pragma unroll
                for (int nf = 0; nf < 4; nf++) {
                    mma_bf16(acc[mf][nf], afh, bfh[nf]);
                    mma_bf16(acc[mf][nf], afh, bfl[nf]);
                    mma_bf16(acc[mf][nf], afl, bfh[nf]);
                }
            }
        }
    };

    stage(0);
    for (int c = 0; c < KC; c++) {
        if (c + 1 < KC) {
            stage(c + 1);
            asm volatile("cp.async.wait_group 1;");
        } else {
            asm volatile("cp.async.wait_group 0;");
        }
        __syncthreads();
        compute(c & 1);
        __syncthreads();
    }

    // epilogue
#pragma unroll
    for (int mf = 0; mf < 4; mf++) {
        int r0 = m0 + wm + mf * 16 + (lid >> 2);
#pragma unroll
        for (int hh = 0; hh < 2; hh++) {
            int rr = r0 + hh * 8;
            if (rr >= nrows) continue;
            float wsc = 1.f;
            float* dst;
            if (EMODE == 1) {
                int slot = seg + rr;
                int tk = g_tk[slot];
                wsc = g_w[slot];
                dst = (float*)(g_scratch + O_PART) + (size_t)tk * HDIM + (size_t)nb * 128;
            } else {
                float* ob = ext_out ? ext_out : (float*)(g_scratch + out_off);
                dst = ob + (size_t)(seg + rr) * ND + (size_t)nb * 128;
            }
#pragma unroll
            for (int nf = 0; nf < 4; nf++) {
                int col = wn + nf * 8 + (lid & 3) * 2;
                float2 v;
                v.x = acc[mf][nf][hh * 2 + 0] * wsc;
                v.y = acc[mf][nf][hh * 2 + 1] * wsc;
                *(float2*)(dst + col) = v;
            }
        }
    }
}

// ---------------------------------------------------------------------------
// combine
// ---------------------------------------------------------------------------
__global__ void combine_kernel(float* __restrict__ out) {
    size_t i = (size_t)blockIdx.x * blockDim.x + threadIdx.x;
    size_t v = i * 4;
    int t = (int)(v / HDIM);
    int h = (int)(v % HDIM);
    const float* part = (const float*)(g_scratch + O_PART);
    float4 o = *(float4*)&out[v];
#pragma unroll
    for (int k = 0; k < TOPK; k++) {
        const float4 p = *(const float4*)&part[(size_t)(t * TOPK + k) * HDIM + h];
        o.x += p.x; o.y += p.y; o.z += p.z; o.w += p.w;
    }
    *(float4*)&out[v] = o;
}

// ---------------------------------------------------------------------------
// launch — R12/R13 order preserved (my idx 3 = shared gate GEMM, ncu target)
// ---------------------------------------------------------------------------
extern "C" void kernel_launch(void* const* d_in, const int* in_sizes, int n_in,
                              void* d_out, int out_size) {
    const float* hidden      = (const float*)d_in[0];
    const float* gate_weight = (const float*)d_in[1];
    const float* bias        = (const float*)d_in[2];
    const float* gate_w      = (const float*)d_in[3];
    const float* up_w        = (const float*)d_in[4];
    const float* down_w      = (const float*)d_in[5];
    const float* sh_gate_w   = (const float*)d_in[6];
    const float* sh_up_w     = (const float*)d_in[7];
    const float* sh_down_w   = (const float*)d_in[8];
    float* out = (float*)d_out;

    cudaFuncSetAttribute(mma_gemm<2048, 1024, 1, 0>,
                         cudaFuncAttributeMaxDynamicSharedMemorySize, GSMEM_BYTES);
    cudaFuncSetAttribute(mma_gemm<1024, 2048, 2, 1>,
                         cudaFuncAttributeMaxDynamicSharedMemorySize, GSMEM_BYTES);
    cudaFuncSetAttribute(mma_gemm<2048, 2048, 0, 0>,
                         cudaFuncAttributeMaxDynamicSharedMemorySize, GSMEM_BYTES);

    // idx 0: hidden split
    {
        int np = T_TOK * HDIM / 2;
        prep_split<<<(np + 255) / 256, 256>>>(hidden, O_HID_HI, O_HID_LO, np);
    }
    // idx 1-2: shared gate/up weights
    {
        int np = FSH * HDIM / 2;
        prep_weight<FSH, HDIM><<<(np + 255) / 256, 256>>>(sh_gate_w, O_WSG_HI, O_WSG_LO, np);
        prep_weight<FSH, HDIM><<<(np + 255) / 256, 256>>>(sh_up_w,   O_WSU_HI, O_WSU_LO, np);
    }

    // idx 3: shared-expert GATE GEMM  <-- ncu profiles this
    mma_gemm<2048, 2048, 0, 0><<<dim3(FSH / 128, T_TOK / 256, 1), GT, GSMEM_BYTES>>>(
        O_HID_HI, O_HID_LO, O_WSG_HI, O_WSG_LO, O_SHG, nullptr);
    // idx 4: shared up GEMM
    mma_gemm<2048, 2048, 0, 0><<<dim3(FSH / 128, T_TOK / 256, 1), GT, GSMEM_BYTES>>>(
        O_HID_HI, O_HID_LO, O_WSU_HI, O_WSU_LO, O_SHU, nullptr);
    // idx 5: shared act
    {
        int np = T_TOK * FSH / 2;
        act_kernel<<<(np + 255) / 256, 256>>>(O_SHG, O_SHU, O_SHA_HI, O_SHA_LO, np);
    }
    // idx 6: shared down weights
    {
        int np = FSH * HDIM / 2;
        prep_weight<HDIM, FSH><<<(np + 255) / 256, 256>>>(sh_down_w, O_WSD_HI, O_WSD_LO, np);
    }
    // idx 7: shared down GEMM -> out
    mma_gemm<2048, 2048, 0, 0><<<dim3(HDIM / 128, T_TOK / 256, 1), GT, GSMEM_BYTES>>>(
        O_SHA_HI, O_SHA_LO, O_WSD_HI, O_WSD_LO, 0, out);

    // routed weight prep
    {
        int np = NEXP * FMOE * HDIM / 2;
        prep_weight<FMOE, HDIM><<<(np + 255) / 256, 256>>>(gate_w, O_WG_HI, O_WG_LO, np);
        prep_weight<FMOE, HDIM><<<(np + 255) / 256, 256>>>(up_w,   O_WU_HI, O_WU_LO, np);
    }
    {
        int np = NEXP * HDIM * FMOE / 2;
        prep_weight<HDIM, FMOE><<<(np + 255) / 256, 256>>>(down_w, O_WD_HI, O_WD_LO, np);
    }

    // routing
    zero_kernel<<<1, 32>>>();
    router_kernel<<<T_TOK, 512>>>(hidden, gate_weight, bias);
    offsets_kernel<<<1, 1>>>();
    dispatch_kernel<<<(T_TOK + 255) / 256, 256>>>();

    // routed experts (M-tiles of 256)
    mma_gemm<2048, 1024, 1, 0><<<dim3(FMOE / 128, T_TOK / 256, NEXP), GT, GSMEM_BYTES>>>(
        O_HID_HI, O_HID_LO, O_WG_HI, O_WG_LO, O_GBUF, nullptr);
    mma_gemm<2048, 1024, 1, 0><<<dim3(FMOE / 128, T_TOK / 256, NEXP), GT, GSMEM_BYTES>>>(
        O_HID_HI, O_HID_LO, O_WU_HI, O_WU_LO, O_UBUF, nullptr);
    {
        int np = NASS * FMOE / 2;
        act_kernel<<<(np + 255) / 256, 256>>>(O_GBUF, O_UBUF, O_ACT_HI, O_ACT_LO, np);
    }
    mma_gemm<1024, 2048, 2, 1><<<dim3(HDIM / 128, T_TOK / 256, NEXP), GT, GSMEM_BYTES>>>(
        O_ACT_HI, O_ACT_LO, O_WD_HI, O_WD_LO, 0, nullptr);

    // combine (routed partials on top of shared output already in `out`)
    combine_kernel<<<(T_TOK * HDIM / 4) / 256, 256>>>(out);
}

// round 15
// speedup vs baseline: 1.0650x; 1.0650x over previous
#include <cuda_runtime.h>
#include <cuda_bf16.h>
#include <math.h>
#include <stdint.h>

// ---------------------------------------------------------------------------
// Problem constants
// ---------------------------------------------------------------------------
constexpr int T_TOK = 4096;
constexpr int HDIM  = 2048;
constexpr int FMOE  = 1024;
constexpr int FSH   = 2048;
constexpr int NEXP  = 16;
constexpr int TOPK  = 4;
constexpr int NGRP  = 4;
constexpr int EPG   = NEXP / NGRP;
constexpr int NASS  = T_TOK * TOPK;
constexpr float RSCALE = 2.5f;

// ---------------------------------------------------------------------------
// Scratch layout (identical to R6/R12/R13)
// ---------------------------------------------------------------------------
constexpr size_t SZ_RW  = (size_t)NEXP * FMOE * HDIM * 2;
constexpr size_t SZ_DW  = (size_t)NEXP * HDIM * FMOE * 2;
constexpr size_t SZ_SW  = (size_t)FSH * HDIM * 2;
constexpr size_t SZ_HID = (size_t)T_TOK * HDIM * 2;
constexpr size_t SZ_GU  = (size_t)NASS * FMOE * 4;
constexpr size_t SZ_ACT = (size_t)NASS * FMOE * 2;
constexpr size_t SZ_SHB = (size_t)T_TOK * FSH * 4;
constexpr size_t SZ_SHA = (size_t)T_TOK * FSH * 2;
constexpr size_t SZ_PART= (size_t)NASS * HDIM * 4;

constexpr size_t O_WG_HI  = 0;
constexpr size_t O_WG_LO  = O_WG_HI  + SZ_RW;
constexpr size_t O_WU_HI  = O_WG_LO  + SZ_RW;
constexpr size_t O_WU_LO  = O_WU_HI  + SZ_RW;
constexpr size_t O_WD_HI  = O_WU_LO  + SZ_RW;
constexpr size_t O_WD_LO  = O_WD_HI  + SZ_DW;
constexpr size_t O_WSG_HI = O_WD_LO  + SZ_DW;
constexpr size_t O_WSG_LO = O_WSG_HI + SZ_SW;
constexpr size_t O_WSU_HI = O_WSG_LO + SZ_SW;
constexpr size_t O_WSU_LO = O_WSU_HI + SZ_SW;
constexpr size_t O_WSD_HI = O_WSU_LO + SZ_SW;
constexpr size_t O_WSD_LO = O_WSD_HI + SZ_SW;
constexpr size_t O_HID_HI = O_WSD_LO + SZ_SW;
constexpr size_t O_HID_LO = O_HID_HI + SZ_HID;
constexpr size_t O_GBUF   = O_HID_LO + SZ_HID;
constexpr size_t O_UBUF   = O_GBUF   + SZ_GU;
constexpr size_t O_ACT_HI = O_UBUF   + SZ_GU;
constexpr size_t O_ACT_LO = O_ACT_HI + SZ_ACT;
constexpr size_t O_SHG    = O_ACT_LO + SZ_ACT;
constexpr size_t O_SHU    = O_SHG    + SZ_SHB;
constexpr size_t O_SHA_HI = O_SHU    + SZ_SHB;
constexpr size_t O_SHA_LO = O_SHA_HI + SZ_SHA;
constexpr size_t O_PART   = O_SHA_LO + SZ_SHA;
constexpr size_t O_TOTAL  = O_PART   + SZ_PART;

__device__ __align__(256) char g_scratch[O_TOTAL];

__device__ int   g_counts[NEXP];
__device__ int   g_fill[NEXP];
__device__ int   g_offsets[NEXP + 1];
__device__ int   g_topk_idx[NASS];
__device__ float g_topk_w[NASS];
__device__ int   g_tk[NASS];
__device__ float g_w[NASS];

// ---------------------------------------------------------------------------
// Helpers
// ---------------------------------------------------------------------------
__device__ __forceinline__ uint32_t smem_to_u32(const void* p) {
    uint32_t a;
    asm("{ .reg .u64 t; cvta.to.shared.u64 t, %1; cvt.u32.u64 %0, t; }"
        : "=r"(a) : "l"(p));
    return a;
}
__device__ __forceinline__ uint32_t swz32(uint32_t x) {
    return x ^ ((x >> 3) & 0x70u);
}
__device__ __forceinline__ float silu(float x) { return x / (1.f + expf(-x)); }

__device__ __forceinline__ void cp16(uint32_t dst, const void* src) {
    asm volatile("cp.async.cg.shared.global [%0], [%1], 16;" :: "r"(dst), "l"(src));
}
__device__ __forceinline__ void ldsm_x4(uint32_t* r, uint32_t addr) {
    asm volatile("ldmatrix.sync.aligned.m8n8.x4.shared.b16 {%0,%1,%2,%3}, [%4];"
        : "=r"(r[0]), "=r"(r[1]), "=r"(r[2]), "=r"(r[3]) : "r"(addr));
}
__device__ __forceinline__ void mma_bf16(float* c, const uint32_t* a, const uint32_t* b) {
    asm volatile(
        "mma.sync.aligned.m16n8k16.row.col.f32.bf16.bf16.f32 "
        "{%0,%1,%2,%3}, {%4,%5,%6,%7}, {%8,%9}, {%0,%1,%2,%3};"
        : "+f"(c[0]), "+f"(c[1]), "+f"(c[2]), "+f"(c[3])
        : "r"(a[0]), "r"(a[1]), "r"(a[2]), "r"(a[3]), "r"(b[0]), "r"(b[1]));
}

// ---------------------------------------------------------------------------
// zero counters
// ---------------------------------------------------------------------------
__global__ void zero_kernel() {
    int i = threadIdx.x;
    if (i < NEXP) { g_counts[i] = 0; g_fill[i] = 0; }
}

// ---------------------------------------------------------------------------
// Router (validated R4/R6)
// ---------------------------------------------------------------------------
__global__ void router_kernel(const float* __restrict__ hidden,
                              const float* __restrict__ gw,
                              const float* __restrict__ bias) {
    int t    = blockIdx.x;
    int lane = threadIdx.x & 31;
    int wid  = threadIdx.x >> 5;
    __shared__ float slog[NEXP];

    const float* hrow = hidden + (size_t)t * HDIM;
    const float* wrow = gw + (size_t)wid * HDIM;
    float s = 0.f;
    for (int h = lane; h < HDIM; h += 32) s += hrow[h] * wrow[h];
#pragma unroll
    for (int o = 16; o > 0; o >>= 1) s += __shfl_down_sync(0xffffffffu, s, o);
    if (lane == 0) slog[wid] = s;
    __syncthreads();

    if (threadIdx.x == 0) {
        float sc[NEXP], s4c[NEXP];
#pragma unroll
        for (int e = 0; e < NEXP; e++) {
            float sg = 1.f / (1.f + expf(-slog[e]));
            sc[e] = sg; s4c[e] = sg + bias[e];
        }
        float gsc[NGRP];
#pragma unroll
        for (int g = 0; g < NGRP; g++) {
            int i1 = 0; float v1 = -INFINITY;
            for (int j = 0; j < EPG; j++) {
                float v = s4c[g * EPG + j];
                if (v > v1) { v1 = v; i1 = j; }
            }
            float v2 = -INFINITY;
            for (int j = 0; j < EPG; j++) {
                if (j == i1) continue;
                float v = s4c[g * EPG + j];
                if (v > v2) v2 = v;
            }
            gsc[g] = v1 + v2;
        }
        int g0 = 0; float gv0 = -INFINITY;
        for (int g = 0; g < NGRP; g++) if (gsc[g] > gv0) { gv0 = gsc[g]; g0 = g; }
        int g1 = -1; float gv1 = -INFINITY;
        for (int g = 0; g < NGRP; g++) {
            if (g == g0) continue;
            if (gsc[g] > gv1) { gv1 = gsc[g]; g1 = g; }
        }
        float masked[NEXP];
#pragma unroll
        for (int e = 0; e < NEXP; e++) {
            int g = e / EPG;
            masked[e] = (g == g0 || g == g1) ? s4c[e] : -INFINITY;
        }
        int idx[TOPK]; float wraw[TOPK]; float wsum = 0.f;
#pragma unroll
        for (int k = 0; k < TOPK; k++) {
            int best = 0; float bv = -INFINITY;
            for (int e = 0; e < NEXP; e++)
                if (masked[e] > bv) { bv = masked[e]; best = e; }
            masked[best] = -INFINITY;
            idx[k] = best; wraw[k] = sc[best]; wsum += sc[best];
        }
        float inv = RSCALE / (wsum + 1e-20f);
#pragma unroll
        for (int k = 0; k < TOPK; k++) {
            g_topk_idx[t * TOPK + k] = idx[k];
            g_topk_w[t * TOPK + k]   = wraw[k] * inv;
            atomicAdd(&g_counts[idx[k]], 1);
        }
    }
}

__global__ void offsets_kernel() {
    if (threadIdx.x == 0) {
        int acc = 0;
        for (int e = 0; e < NEXP; e++) { g_offsets[e] = acc; acc += g_counts[e]; }
        g_offsets[NEXP] = acc;
    }
}

__global__ void dispatch_kernel() {
    int t = blockIdx.x * blockDim.x + threadIdx.x;
    if (t >= T_TOK) return;
#pragma unroll
    for (int k = 0; k < TOPK; k++) {
        int e    = g_topk_idx[t * TOPK + k];
        int pos  = atomicAdd(&g_fill[e], 1);
        int slot = g_offsets[e] + pos;
        g_tk[slot] = t * TOPK + k;
        g_w[slot]  = g_topk_w[t * TOPK + k];
    }
}

// ---------------------------------------------------------------------------
// split helpers: x = hi(bf16) + lo(bf16)
// ---------------------------------------------------------------------------
__device__ __forceinline__ void split_pair(float a0, float a1,
                                           __nv_bfloat162& hp, __nv_bfloat162& lp) {
    hp = __floats2bfloat162_rn(a0, a1);
    float l0 = a0 - __bfloat162float(__low2bfloat16(hp));
    float l1 = a1 - __bfloat162float(__high2bfloat16(hp));
    lp = __floats2bfloat162_rn(l0, l1);
}

// ---------------------------------------------------------------------------
// prep kernels (exactly as R6/R12/R13)
// ---------------------------------------------------------------------------
template <int F, int K>
__global__ void prep_weight(const float* __restrict__ src,
                            size_t hi_off, size_t lo_off, int npairs) {
    int i = blockIdx.x * blockDim.x + threadIdx.x;
    if (i >= npairs) return;
    size_t elem = (size_t)i * 2;
    int k = (int)(elem % K);
    int f = (int)((elem / K) % F);
    int e = (int)(elem / ((size_t)K * F));
    float2 v = *(const float2*)(src + elem);
    __nv_bfloat162 hp, lp;
    split_pair(v.x, v.y, hp, lp);
    int n = f >> 7, r = f & 127, c = k >> 6, col = k & 63;
    size_t tb = ((size_t)(e * (F >> 7) + n) * (K >> 6) + c) * 16384;
    int off = r * 128 + col * 2;
    int sw = off ^ ((off >> 3) & 0x70);
    *(__nv_bfloat162*)(g_scratch + hi_off + tb + sw) = hp;
    *(__nv_bfloat162*)(g_scratch + lo_off + tb + sw) = lp;
}

__global__ void prep_split(const float* __restrict__ src,
                           size_t hi_off, size_t lo_off, int npairs) {
    int i = blockIdx.x * blockDim.x + threadIdx.x;
    if (i >= npairs) return;
    float2 v = *(const float2*)(src + (size_t)i * 2);
    __nv_bfloat162 hp, lp;
    split_pair(v.x, v.y, hp, lp);
    ((__nv_bfloat162*)(g_scratch + hi_off))[i] = hp;
    ((__nv_bfloat162*)(g_scratch + lo_off))[i] = lp;
}

__global__ void act_kernel(size_t g_off, size_t u_off,
                           size_t hi_off, size_t lo_off, int npairs) {
    int i = blockIdx.x * blockDim.x + threadIdx.x;
    if (i >= npairs) return;
    float2 g2 = ((const float2*)(g_scratch + g_off))[i];
    float2 u2 = ((const float2*)(g_scratch + u_off))[i];
    float a0 = silu(g2.x) * u2.x;
    float a1 = silu(g2.y) * u2.y;
    __nv_bfloat162 hp, lp;
    split_pair(a0, a1, hp, lp);
    ((__nv_bfloat162*)(g_scratch + hi_off))[i] = hp;
    ((__nv_bfloat162*)(g_scratch + lo_off))[i] = lp;
}

// ---------------------------------------------------------------------------
// Grouped GEMM — R13 shape (512 threads, CTA 128x128, warp 32x32, occ 25%)
// + 3-stage cp.async pipeline with ONE sync per chunk, stage issued BEFORE
// compute. Buffer safety: at iter c, stage(c+2) writes buf (c+2)%3 ==
// (c-1)%3; the sync at top of iter c proves all warps finished compute(c-1).
// AMODE: 0 plain rows, 1 gather hidden rows via g_tk, 2 slot rows.
// EMODE: 0 plain store, 1 scale by g_w + scatter to g_part[tk].
// Stage layout per buffer: Ah[0,16K) Al[16K,32K) Bh[32K,48K) Bl[48K,64K).
// ---------------------------------------------------------------------------
constexpr int NSTAGE = 3;
constexpr int GSMEM_BYTES = NSTAGE * 65536;   // 192 KB
constexpr int GT = 512;

template <int KD, int ND, int AMODE, int EMODE>
__global__ void __launch_bounds__(GT)
mma_gemm(size_t a_hi_off, size_t a_lo_off,
         size_t w_hi_off, size_t w_lo_off,
         size_t out_off, float* ext_out) {
    constexpr int KC = KD / 64;
    constexpr int NT = ND / 128;
    extern __shared__ char smem[];
    uint32_t sb = smem_to_u32(smem);

    int e, seg, nrows;
    if (AMODE == 0) { e = 0; seg = 0; nrows = T_TOK; }
    else { e = blockIdx.z; seg = g_offsets[e]; nrows = g_offsets[e + 1] - seg; }
    int m0 = blockIdx.y * 128;
    if (m0 >= nrows) return;
    int nb = blockIdx.x;

    int tid = threadIdx.x, wid = tid >> 5, lid = tid & 31;

    // ---- A staging: thread = (row, quarter of 128B row); 2x16B per image ----
    const __nv_bfloat16* a_hi = (const __nv_bfloat16*)(g_scratch + a_hi_off);
    const __nv_bfloat16* a_lo = (const __nv_bfloat16*)(g_scratch + a_lo_off);
    int r = tid >> 2, q = tid & 3;
    int mrow = m0 + r;
    bool av = mrow < nrows;
    size_t arow;
    if (AMODE == 1)      arow = (size_t)(g_tk[seg + (av ? mrow : m0)] >> 2);
    else if (AMODE == 2) arow = (size_t)(seg + (av ? mrow : m0));
    else                 arow = (size_t)(av ? mrow : m0);
    const char* ah0 = (const char*)(a_hi + arow * KD + q * 16);
    const char* al0 = (const char*)(a_lo + arow * KD + q * 16);
    uint32_t asw[2];
#pragma unroll
    for (int u = 0; u < 2; u++)
        asw[u] = swz32((uint32_t)(r * 128 + q * 32 + u * 16));

    // ---- B: preswizzled 16KB tiles, identity copy; 2x16B per image ----
    size_t wtile = (size_t)(e * NT + nb) * KC;
    const char* bh0 = g_scratch + w_hi_off + wtile * 16384 + tid * 32;
    const char* bl0 = g_scratch + w_lo_off + wtile * 16384 + tid * 32;

    // warp layout: 4 m-warps x 4 n-warps, warp tile 32x32
    int wm = (wid & 3) * 32, wn = (wid >> 2) * 32;
    float acc[2][4][4];
#pragma unroll
    for (int a = 0; a < 2; a++)
#pragma unroll
        for (int b = 0; b < 4; b++)
#pragma unroll
            for (int c2 = 0; c2 < 4; c2++) acc[a][b][c2] = 0.f;

    auto stage = [&](int c) {
        uint32_t X = sb + (uint32_t)(c % NSTAGE) * 65536u;
        const char* ah = ah0 + (size_t)c * 128;
        const char* al = al0 + (size_t)c * 128;
        const char* bh = bh0 + (size_t)c * 16384;
        const char* bl = bl0 + (size_t)c * 16384;
#pragma unroll
        for (int u = 0; u < 2; u++) {
            cp16(X + asw[u],         ah + u * 16);
            cp16(X + 16384 + asw[u], al + u * 16);
        }
#pragma unroll
        for (int u = 0; u < 2; u++) {
            cp16(X + 32768 + tid * 32 + u * 16, bh + u * 16);
            cp16(X + 49152 + tid * 32 + u * 16, bl + u * 16);
        }
        asm volatile("cp.async.commit_group;");
    };

    auto compute = [&](int s) {
        uint32_t X = sb + (uint32_t)s * 65536u;
        int g = lid >> 3;
#pragma unroll
        for (int k16 = 0; k16 < 4; k16++) {
            int kb = k16 * 32;
            uint32_t afh[2][4], afl[2][4];
#pragma unroll
            for (int mf = 0; mf < 2; mf++) {
                int rr = wm + mf * 16 + (lid & 7) + (g & 1) * 8;
                int bb = kb + (g >> 1) * 16;
                uint32_t ad = X + swz32((uint32_t)(rr * 128 + bb));
                ldsm_x4(afh[mf], ad);
                ldsm_x4(afl[mf], ad + 16384);
            }
            uint32_t bfh[4][2], bfl[4][2];
#pragma unroll
            for (int nq = 0; nq < 2; nq++) {
                int rr = wn + nq * 16 + (lid & 7) + (g >> 1) * 8;
                int bb = kb + (g & 1) * 16;
                uint32_t ad = X + 32768 + swz32((uint32_t)(rr * 128 + bb));
                uint32_t t4[4];
                ldsm_x4(t4, ad);
                bfh[2*nq][0] = t4[0]; bfh[2*nq][1] = t4[1];
                bfh[2*nq+1][0] = t4[2]; bfh[2*nq+1][1] = t4[3];
                ldsm_x4(t4, ad + 16384);
                bfl[2*nq][0] = t4[0]; bfl[2*nq][1] = t4[1];
                bfl[2*nq+1][0] = t4[2]; bfl[2*nq+1][1] = t4[3];
            }
            // fragment-major 3-term (R6/R13 ordering — measured best)
#pragma unroll
            for (int mf = 0; mf < 2; mf++)
#pragma unroll
                for (int nf = 0; nf < 4; nf++) {
                    mma_bf16(acc[mf][nf], afh[mf], bfh[nf]);
                    mma_bf16(acc[mf][nf], afh[mf], bfl[nf]);
                    mma_bf16(acc[mf][nf], afl[mf], bfh[nf]);
                }
        }
    };

    // 3-stage pipeline, one sync per chunk, stage before compute
    stage(0);
    stage(1);
    for (int c = 0; c < KC; c++) {
        if (c + 1 < KC) {
            asm volatile("cp.async.wait_group 1;");
        } else {
            asm volatile("cp.async.wait_group 0;");
        }
        __syncthreads();
        if (c + 2 < KC) stage(c + 2);
        compute(c % NSTAGE);
    }

    // epilogue
#pragma unroll
    for (int mf = 0; mf < 2; mf++) {
        int r0 = m0 + wm + mf * 16 + (lid >> 2);
#pragma unroll
        for (int hh = 0; hh < 2; hh++) {
            int rr = r0 + hh * 8;
            if (rr - m0 >= 128 || rr >= nrows) continue;
            float wsc = 1.f;
            float* dst;
            if (EMODE == 1) {
                int slot = seg + rr;
                int tk = g_tk[slot];
                wsc = g_w[slot];
                dst = (float*)(g_scratch + O_PART) + (size_t)tk * HDIM + (size_t)nb * 128;
            } else {
                float* ob = ext_out ? ext_out : (float*)(g_scratch + out_off);
                dst = ob + (size_t)(seg + rr) * ND + (size_t)nb * 128;
            }
#pragma unroll
            for (int nf = 0; nf < 4; nf++) {
                int col = wn + nf * 8 + (lid & 3) * 2;
                float2 v;
                v.x = acc[mf][nf][hh * 2 + 0] * wsc;
                v.y = acc[mf][nf][hh * 2 + 1] * wsc;
                *(float2*)(dst + col) = v;
            }
        }
    }
}

// ---------------------------------------------------------------------------
// combine
// ---------------------------------------------------------------------------
__global__ void combine_kernel(float* __restrict__ out) {
    size_t i = (size_t)blockIdx.x * blockDim.x + threadIdx.x;
    size_t v = i * 4;
    int t = (int)(v / HDIM);
    int h = (int)(v % HDIM);
    const float* part = (const float*)(g_scratch + O_PART);
    float4 o = *(float4*)&out[v];
#pragma unroll
    for (int k = 0; k < TOPK; k++) {
        const float4 p = *(const float4*)&part[(size_t)(t * TOPK + k) * HDIM + h];
        o.x += p.x; o.y += p.y; o.z += p.z; o.w += p.w;
    }
    *(float4*)&out[v] = o;
}

// ---------------------------------------------------------------------------
// launch — R12/R13 order preserved (my idx 3 = shared gate GEMM, ncu target)
// ---------------------------------------------------------------------------
extern "C" void kernel_launch(void* const* d_in, const int* in_sizes, int n_in,
                              void* d_out, int out_size) {
    const float* hidden      = (const float*)d_in[0];
    const float* gate_weight = (const float*)d_in[1];
    const float* bias        = (const float*)d_in[2];
    const float* gate_w      = (const float*)d_in[3];
    const float* up_w        = (const float*)d_in[4];
    const float* down_w      = (const float*)d_in[5];
    const float* sh_gate_w   = (const float*)d_in[6];
    const float* sh_up_w     = (const float*)d_in[7];
    const float* sh_down_w   = (const float*)d_in[8];
    float* out = (float*)d_out;

    cudaFuncSetAttribute(mma_gemm<2048, 1024, 1, 0>,
                         cudaFuncAttributeMaxDynamicSharedMemorySize, GSMEM_BYTES);
    cudaFuncSetAttribute(mma_gemm<1024, 2048, 2, 1>,
                         cudaFuncAttributeMaxDynamicSharedMemorySize, GSMEM_BYTES);
    cudaFuncSetAttribute(mma_gemm<2048, 2048, 0, 0>,
                         cudaFuncAttributeMaxDynamicSharedMemorySize, GSMEM_BYTES);

    // idx 0: hidden split
    {
        int np = T_TOK * HDIM / 2;
        prep_split<<<(np + 255) / 256, 256>>>(hidden, O_HID_HI, O_HID_LO, np);
    }
    // idx 1-2: shared gate/up weights
    {
        int np = FSH * HDIM / 2;
        prep_weight<FSH, HDIM><<<(np + 255) / 256, 256>>>(sh_gate_w, O_WSG_HI, O_WSG_LO, np);
        prep_weight<FSH, HDIM><<<(np + 255) / 256, 256>>>(sh_up_w,   O_WSU_HI, O_WSU_LO, np);
    }

    // idx 3: shared-expert GATE GEMM  <-- ncu profiles this
    mma_gemm<2048, 2048, 0, 0><<<dim3(FSH / 128, T_TOK / 128, 1), GT, GSMEM_BYTES>>>(
        O_HID_HI, O_HID_LO, O_WSG_HI, O_WSG_LO, O_SHG, nullptr);
    // idx 4: shared up GEMM
    mma_gemm<2048, 2048, 0, 0><<<dim3(FSH / 128, T_TOK / 128, 1), GT, GSMEM_BYTES>>>(
        O_HID_HI, O_HID_LO, O_WSU_HI, O_WSU_LO, O_SHU, nullptr);
    // idx 5: shared act
    {
        int np = T_TOK * FSH / 2;
        act_kernel<<<(np + 255) / 256, 256>>>(O_SHG, O_SHU, O_SHA_HI, O_SHA_LO, np);
    }
    // idx 6: shared down weights
    {
        int np = FSH * HDIM / 2;
        prep_weight<HDIM, FSH><<<(np + 255) / 256, 256>>>(sh_down_w, O_WSD_HI, O_WSD_LO, np);
    }
    // idx 7: shared down GEMM -> out
    mma_gemm<2048, 2048, 0, 0><<<dim3(HDIM / 128, T_TOK / 128, 1), GT, GSMEM_BYTES>>>(
        O_SHA_HI, O_SHA_LO, O_WSD_HI, O_WSD_LO, 0, out);

    // routed weight prep
    {
        int np = NEXP * FMOE * HDIM / 2;
        prep_weight<FMOE, HDIM><<<(np + 255) / 256, 256>>>(gate_w, O_WG_HI, O_WG_LO, np);
        prep_weight<FMOE, HDIM><<<(np + 255) / 256, 256>>>(up_w,   O_WU_HI, O_WU_LO, np);
    }
    {
        int np = NEXP * HDIM * FMOE / 2;
        prep_weight<HDIM, FMOE><<<(np + 255) / 256, 256>>>(down_w, O_WD_HI, O_WD_LO, np);
    }

    // routing
    zero_kernel<<<1, 32>>>();
    router_kernel<<<T_TOK, 512>>>(hidden, gate_weight, bias);
    offsets_kernel<<<1, 1>>>();
    dispatch_kernel<<<(T_TOK + 255) / 256, 256>>>();

    // routed experts
    mma_gemm<2048, 1024, 1, 0><<<dim3(FMOE / 128, T_TOK / 128, NEXP), GT, GSMEM_BYTES>>>(
        O_HID_HI, O_HID_LO, O_WG_HI, O_WG_LO, O_GBUF, nullptr);
    mma_gemm<2048, 1024, 1, 0><<<dim3(FMOE / 128, T_TOK / 128, NEXP), GT, GSMEM_BYTES>>>(
        O_HID_HI, O_HID_LO, O_WU_HI, O_WU_LO, O_UBUF, nullptr);
    {
        int np = NASS * FMOE / 2;
        act_kernel<<<(np + 255) / 256, 256>>>(O_GBUF, O_UBUF, O_ACT_HI, O_ACT_LO, np);
    }
    mma_gemm<1024, 2048, 2, 1><<<dim3(HDIM / 128, T_TOK / 128, NEXP), GT, GSMEM_BYTES>>>(
        O_ACT_HI, O_ACT_LO, O_WD_HI, O_WD_LO, 0, nullptr);

    // combine (routed partials on top of shared output already in `out`)
    combine_kernel<<<(T_TOK * HDIM / 4) / 256, 256>>>(out);
}

// round 17
// speedup vs baseline: 1.1381x; 1.0687x over previous
#include <cuda_runtime.h>
#include <cuda_bf16.h>
#include <math.h>
#include <stdint.h>

// ---------------------------------------------------------------------------
// Problem constants
// ---------------------------------------------------------------------------
constexpr int T_TOK = 4096;
constexpr int HDIM  = 2048;
constexpr int FMOE  = 1024;
constexpr int FSH   = 2048;
constexpr int NEXP  = 16;
constexpr int TOPK  = 4;
constexpr int NGRP  = 4;
constexpr int EPG   = NEXP / NGRP;
constexpr int NASS  = T_TOK * TOPK;
constexpr float RSCALE = 2.5f;

// ---------------------------------------------------------------------------
// Scratch layout
// ---------------------------------------------------------------------------
constexpr size_t SZ_RW  = (size_t)NEXP * FMOE * HDIM * 2;
constexpr size_t SZ_DW  = (size_t)NEXP * HDIM * FMOE * 2;
constexpr size_t SZ_SW  = (size_t)FSH * HDIM * 2;
constexpr size_t SZ_HID = (size_t)T_TOK * HDIM * 2;
constexpr size_t SZ_GU  = (size_t)NASS * FMOE * 4;
constexpr size_t SZ_ACT = (size_t)NASS * FMOE * 2;
constexpr size_t SZ_SHB = (size_t)T_TOK * FSH * 4;
constexpr size_t SZ_SHA = (size_t)T_TOK * FSH * 2;
constexpr size_t SZ_PART= (size_t)NASS * HDIM * 4;

constexpr size_t O_WG_HI  = 0;
constexpr size_t O_WG_LO  = O_WG_HI  + SZ_RW;
constexpr size_t O_WU_HI  = O_WG_LO  + SZ_RW;
constexpr size_t O_WU_LO  = O_WU_HI  + SZ_RW;
constexpr size_t O_WD_HI  = O_WU_LO  + SZ_RW;
constexpr size_t O_WD_LO  = O_WD_HI  + SZ_DW;
constexpr size_t O_WSG_HI = O_WD_LO  + SZ_DW;
constexpr size_t O_WSG_LO = O_WSG_HI + SZ_SW;
constexpr size_t O_WSU_HI = O_WSG_LO + SZ_SW;
constexpr size_t O_WSU_LO = O_WSU_HI + SZ_SW;
constexpr size_t O_WSD_HI = O_WSU_LO + SZ_SW;
constexpr size_t O_WSD_LO = O_WSD_HI + SZ_SW;
constexpr size_t O_HID_HI = O_WSD_LO + SZ_SW;
constexpr size_t O_HID_LO = O_HID_HI + SZ_HID;
constexpr size_t O_GBUF   = O_HID_LO + SZ_HID;
constexpr size_t O_UBUF   = O_GBUF   + SZ_GU;
constexpr size_t O_ACT_HI = O_UBUF   + SZ_GU;
constexpr size_t O_ACT_LO = O_ACT_HI + SZ_ACT;
constexpr size_t O_SHG    = O_ACT_LO + SZ_ACT;
constexpr size_t O_SHU    = O_SHG    + SZ_SHB;
constexpr size_t O_SHA_HI = O_SHU    + SZ_SHB;
constexpr size_t O_SHA_LO = O_SHA_HI + SZ_SHA;
constexpr size_t O_PART   = O_SHA_LO + SZ_SHA;
constexpr size_t O_TOTAL  = O_PART   + SZ_PART;

__device__ __align__(256) char g_scratch[O_TOTAL];

__device__ int   g_counts[NEXP];
__device__ int   g_fill[NEXP];
__device__ int   g_offsets[NEXP + 1];
__device__ int   g_topk_idx[NASS];
__device__ float g_topk_w[NASS];
__device__ int   g_tk[NASS];
__device__ float g_w[NASS];

// ---------------------------------------------------------------------------
// Helpers
// ---------------------------------------------------------------------------
__device__ __forceinline__ uint32_t smem_to_u32(const void* p) {
    uint32_t a;
    asm("{ .reg .u64 t; cvta.to.shared.u64 t, %1; cvt.u32.u64 %0, t; }"
        : "=r"(a) : "l"(p));
    return a;
}
__device__ __forceinline__ uint32_t swz32(uint32_t x) {
    return x ^ ((x >> 3) & 0x70u);
}
__device__ __forceinline__ float silu(float x) { return x / (1.f + expf(-x)); }

__device__ __forceinline__ void cp16(uint32_t dst, const void* src) {
    asm volatile("cp.async.cg.shared.global [%0], [%1], 16;" :: "r"(dst), "l"(src));
}
__device__ __forceinline__ void ldsm_x4(uint32_t* r, uint32_t addr) {
    asm volatile("ldmatrix.sync.aligned.m8n8.x4.shared.b16 {%0,%1,%2,%3}, [%4];"
        : "=r"(r[0]), "=r"(r[1]), "=r"(r[2]), "=r"(r[3]) : "r"(addr));
}
__device__ __forceinline__ void mma_bf16(float* c, const uint32_t* a, const uint32_t* b) {
    asm volatile(
        "mma.sync.aligned.m16n8k16.row.col.f32.bf16.bf16.f32 "
        "{%0,%1,%2,%3}, {%4,%5,%6,%7}, {%8,%9}, {%0,%1,%2,%3};"
        : "+f"(c[0]), "+f"(c[1]), "+f"(c[2]), "+f"(c[3])
        : "r"(a[0]), "r"(a[1]), "r"(a[2]), "r"(a[3]), "r"(b[0]), "r"(b[1]));
}

// ---------------------------------------------------------------------------
// zero counters
// ---------------------------------------------------------------------------
__global__ void zero_kernel() {
    int i = threadIdx.x;
    if (i < NEXP) { g_counts[i] = 0; g_fill[i] = 0; }
}

// ---------------------------------------------------------------------------
// Router (validated R4/R6)
// ---------------------------------------------------------------------------
__global__ void router_kernel(const float* __restrict__ hidden,
                              const float* __restrict__ gw,
                              const float* __restrict__ bias) {
    int t    = blockIdx.x;
    int lane = threadIdx.x & 31;
    int wid  = threadIdx.x >> 5;
    __shared__ float slog[NEXP];

    const float* hrow = hidden + (size_t)t * HDIM;
    const float* wrow = gw + (size_t)wid * HDIM;
    float s = 0.f;
    for (int h = lane; h < HDIM; h += 32) s += hrow[h] * wrow[h];
#pragma unroll
    for (int o = 16; o > 0; o >>= 1) s += __shfl_down_sync(0xffffffffu, s, o);
    if (lane == 0) slog[wid] = s;
    __syncthreads();

    if (threadIdx.x == 0) {
        float sc[NEXP], s4c[NEXP];
#pragma unroll
        for (int e = 0; e < NEXP; e++) {
            float sg = 1.f / (1.f + expf(-slog[e]));
            sc[e] = sg; s4c[e] = sg + bias[e];
        }
        float gsc[NGRP];
#pragma unroll
        for (int g = 0; g < NGRP; g++) {
            int i1 = 0; float v1 = -INFINITY;
            for (int j = 0; j < EPG; j++) {
                float v = s4c[g * EPG + j];
                if (v > v1) { v1 = v; i1 = j; }
            }
            float v2 = -INFINITY;
            for (int j = 0; j < EPG; j++) {
                if (j == i1) continue;
                float v = s4c[g * EPG + j];
                if (v > v2) v2 = v;
            }
            gsc[g] = v1 + v2;
        }
        int g0 = 0; float gv0 = -INFINITY;
        for (int g = 0; g < NGRP; g++) if (gsc[g] > gv0) { gv0 = gsc[g]; g0 = g; }
        int g1 = -1; float gv1 = -INFINITY;
        for (int g = 0; g < NGRP; g++) {
            if (g == g0) continue;
            if (gsc[g] > gv1) { gv1 = gsc[g]; g1 = g; }
        }
        float masked[NEXP];
#pragma unroll
        for (int e = 0; e < NEXP; e++) {
            int g = e / EPG;
            masked[e] = (g == g0 || g == g1) ? s4c[e] : -INFINITY;
        }
        int idx[TOPK]; float wraw[TOPK]; float wsum = 0.f;
#pragma unroll
        for (int k = 0; k < TOPK; k++) {
            int best = 0; float bv = -INFINITY;
            for (int e = 0; e < NEXP; e++)
                if (masked[e] > bv) { bv = masked[e]; best = e; }
            masked[best] = -INFINITY;
            idx[k] = best; wraw[k] = sc[best]; wsum += sc[best];
        }
        float inv = RSCALE / (wsum + 1e-20f);
#pragma unroll
        for (int k = 0; k < TOPK; k++) {
            g_topk_idx[t * TOPK + k] = idx[k];
            g_topk_w[t * TOPK + k]   = wraw[k] * inv;
            atomicAdd(&g_counts[idx[k]], 1);
        }
    }
}

__global__ void offsets_kernel() {
    if (threadIdx.x == 0) {
        int acc = 0;
        for (int e = 0; e < NEXP; e++) { g_offsets[e] = acc; acc += g_counts[e]; }
        g_offsets[NEXP] = acc;
    }
}

__global__ void dispatch_kernel() {
    int t = blockIdx.x * blockDim.x + threadIdx.x;
    if (t >= T_TOK) return;
#pragma unroll
    for (int k = 0; k < TOPK; k++) {
        int e    = g_topk_idx[t * TOPK + k];
        int pos  = atomicAdd(&g_fill[e], 1);
        int slot = g_offsets[e] + pos;
        g_tk[slot] = t * TOPK + k;
        g_w[slot]  = g_topk_w[t * TOPK + k];
    }
}

// ---------------------------------------------------------------------------
// split helpers: x = hi(bf16) + lo(bf16)
// ---------------------------------------------------------------------------
__device__ __forceinline__ void split_pair(float a0, float a1,
                                           __nv_bfloat162& hp, __nv_bfloat162& lp) {
    hp = __floats2bfloat162_rn(a0, a1);
    float l0 = a0 - __bfloat162float(__low2bfloat16(hp));
    float l1 = a1 - __bfloat162float(__high2bfloat16(hp));
    lp = __floats2bfloat162_rn(l0, l1);
}

// ---------------------------------------------------------------------------
// prep kernels
// ---------------------------------------------------------------------------
template <int F, int K>
__global__ void prep_weight(const float* __restrict__ src,
                            size_t hi_off, size_t lo_off, int npairs) {
    int i = blockIdx.x * blockDim.x + threadIdx.x;
    if (i >= npairs) return;
    size_t elem = (size_t)i * 2;
    int k = (int)(elem % K);
    int f = (int)((elem / K) % F);
    int e = (int)(elem / ((size_t)K * F));
    float2 v = *(const float2*)(src + elem);
    __nv_bfloat162 hp, lp;
    split_pair(v.x, v.y, hp, lp);
    int n = f >> 7, r = f & 127, c = k >> 6, col = k & 63;
    size_t tb = ((size_t)(e * (F >> 7) + n) * (K >> 6) + c) * 16384;
    int off = r * 128 + col * 2;
    int sw = off ^ ((off >> 3) & 0x70);
    *(__nv_bfloat162*)(g_scratch + hi_off + tb + sw) = hp;
    *(__nv_bfloat162*)(g_scratch + lo_off + tb + sw) = lp;
}

__global__ void prep_split(const float* __restrict__ src,
                           size_t hi_off, size_t lo_off, int npairs) {
    int i = blockIdx.x * blockDim.x + threadIdx.x;
    if (i >= npairs) return;
    float2 v = *(const float2*)(src + (size_t)i * 2);
    __nv_bfloat162 hp, lp;
    split_pair(v.x, v.y, hp, lp);
    ((__nv_bfloat162*)(g_scratch + hi_off))[i] = hp;
    ((__nv_bfloat162*)(g_scratch + lo_off))[i] = lp;
}

// ---------------------------------------------------------------------------
// FUSED gate+up GEMM. 512 threads, CTA 128x128, warp 32x32, K chunk 64,
// 2-stage cp.async (96KB/stage), ONE sync per chunk with CORRECT pipeline:
//   stage(0)
//   iter c: wait_group 0   -> stage(c) definitely complete
//           __syncthreads  -> all warps done with compute(c-1)
//           stage(c+1)     -> overlaps with compute(c); writes buf (c+1)&1,
//                             last read by compute(c-1) (safe per the sync)
//           compute(c)
// Per-buffer layout: Ah[0,16K) Al[16K,32K) Bgh[32K,48K) Bgl[48K,64K)
//                    Buh[64K,80K) Bul[80K,96K).
// Epilogue: silu(g)*u -> bf16 hi/lo split into ACT images.
// AMODE: 0 plain token rows, 1 gather hidden rows via g_tk.
// ---------------------------------------------------------------------------
constexpr int GU_STAGE = 98304;
constexpr int GU_SMEM  = 2 * GU_STAGE;       // 192 KB
constexpr int GT = 512;

template <int ND, int AMODE>
__global__ void __launch_bounds__(GT)
gu_mma(size_t a_hi_off, size_t a_lo_off,
       size_t wg_hi_off, size_t wg_lo_off,
       size_t wu_hi_off, size_t wu_lo_off,
       size_t act_hi_off, size_t act_lo_off) {
    constexpr int KD = HDIM;
    constexpr int KC = KD / 64;
    constexpr int NT = ND / 128;
    extern __shared__ char smem[];
    uint32_t sb = smem_to_u32(smem);

    int e, seg, nrows;
    if (AMODE == 0) { e = 0; seg = 0; nrows = T_TOK; }
    else { e = blockIdx.z; seg = g_offsets[e]; nrows = g_offsets[e + 1] - seg; }
    int m0 = blockIdx.y * 128;
    if (m0 >= nrows) return;
    int nb = blockIdx.x;

    int tid = threadIdx.x, wid = tid >> 5, lid = tid & 31;

    // A staging: thread = (row, quarter of 128B row); 2x16B per image
    const __nv_bfloat16* a_hi = (const __nv_bfloat16*)(g_scratch + a_hi_off);
    const __nv_bfloat16* a_lo = (const __nv_bfloat16*)(g_scratch + a_lo_off);
    int r = tid >> 2, q = tid & 3;
    int mrow = m0 + r;
    bool av = mrow < nrows;
    size_t arow;
    if (AMODE == 1) arow = (size_t)(g_tk[seg + (av ? mrow : m0)] >> 2);
    else            arow = (size_t)(av ? mrow : m0);
    const char* ah0 = (const char*)(a_hi + arow * KD + q * 16);
    const char* al0 = (const char*)(a_lo + arow * KD + q * 16);
    uint32_t asw[2];
#pragma unroll
    for (int u = 0; u < 2; u++)
        asw[u] = swz32((uint32_t)(r * 128 + q * 32 + u * 16));

    // B tiles (preswizzled 16KB each): gate and up, hi and lo
    size_t wtile = (size_t)(e * NT + nb) * KC;
    const char* bgh0 = g_scratch + wg_hi_off + wtile * 16384 + tid * 32;
    const char* bgl0 = g_scratch + wg_lo_off + wtile * 16384 + tid * 32;
    const char* buh0 = g_scratch + wu_hi_off + wtile * 16384 + tid * 32;
    const char* bul0 = g_scratch + wu_lo_off + wtile * 16384 + tid * 32;

    int wm = (wid & 3) * 32, wn = (wid >> 2) * 32;
    float accg[2][4][4], accu[2][4][4];
#pragma unroll
    for (int a = 0; a < 2; a++)
#pragma unroll
        for (int b = 0; b < 4; b++)
#pragma unroll
            for (int c2 = 0; c2 < 4; c2++) { accg[a][b][c2] = 0.f; accu[a][b][c2] = 0.f; }

    auto stage = [&](int c) {
        uint32_t X = sb + (uint32_t)(c & 1) * (uint32_t)GU_STAGE;
        const char* ah = ah0 + (size_t)c * 128;
        const char* al = al0 + (size_t)c * 128;
        const char* bgh = bgh0 + (size_t)c * 16384;
        const char* bgl = bgl0 + (size_t)c * 16384;
        const char* buh = buh0 + (size_t)c * 16384;
        const char* bul = bul0 + (size_t)c * 16384;
#pragma unroll
        for (int u = 0; u < 2; u++) {
            cp16(X + asw[u],         ah + u * 16);
            cp16(X + 16384 + asw[u], al + u * 16);
        }
#pragma unroll
        for (int u = 0; u < 2; u++) {
            uint32_t d = X + tid * 32 + u * 16;
            cp16(d + 32768, bgh + u * 16);
            cp16(d + 49152, bgl + u * 16);
            cp16(d + 65536, buh + u * 16);
            cp16(d + 81920, bul + u * 16);
        }
        asm volatile("cp.async.commit_group;");
    };

    auto compute = [&](int s) {
        uint32_t X = sb + (uint32_t)s * (uint32_t)GU_STAGE;
        int g = lid >> 3;
#pragma unroll
        for (int k16 = 0; k16 < 4; k16++) {
            int kb = k16 * 32;
            uint32_t afh[2][4], afl[2][4];
#pragma unroll
            for (int mf = 0; mf < 2; mf++) {
                int rr = wm + mf * 16 + (lid & 7) + (g & 1) * 8;
                int bb = kb + (g >> 1) * 16;
                uint32_t ad = X + swz32((uint32_t)(rr * 128 + bb));
                ldsm_x4(afh[mf], ad);
                ldsm_x4(afl[mf], ad + 16384);
            }
            uint32_t bfh[4][2], bfl[4][2];
            // ---- gate ----
#pragma unroll
            for (int nq = 0; nq < 2; nq++) {
                int rr = wn + nq * 16 + (lid & 7) + (g >> 1) * 8;
                int bb = kb + (g & 1) * 16;
                uint32_t ad = X + 32768 + swz32((uint32_t)(rr * 128 + bb));
                uint32_t t4[4];
                ldsm_x4(t4, ad);
                bfh[2*nq][0] = t4[0]; bfh[2*nq][1] = t4[1];
                bfh[2*nq+1][0] = t4[2]; bfh[2*nq+1][1] = t4[3];
                ldsm_x4(t4, ad + 16384);
                bfl[2*nq][0] = t4[0]; bfl[2*nq][1] = t4[1];
                bfl[2*nq+1][0] = t4[2]; bfl[2*nq+1][1] = t4[3];
            }
#pragma unroll
            for (int mf = 0; mf < 2; mf++)
#pragma unroll
                for (int nf = 0; nf < 4; nf++) {
                    mma_bf16(accg[mf][nf], afh[mf], bfh[nf]);
                    mma_bf16(accg[mf][nf], afh[mf], bfl[nf]);
                    mma_bf16(accg[mf][nf], afl[mf], bfh[nf]);
                }
            // ---- up (reuse B frag regs) ----
#pragma unroll
            for (int nq = 0; nq < 2; nq++) {
                int rr = wn + nq * 16 + (lid & 7) + (g >> 1) * 8;
                int bb = kb + (g & 1) * 16;
                uint32_t ad = X + 65536 + swz32((uint32_t)(rr * 128 + bb));
                uint32_t t4[4];
                ldsm_x4(t4, ad);
                bfh[2*nq][0] = t4[0]; bfh[2*nq][1] = t4[1];
                bfh[2*nq+1][0] = t4[2]; bfh[2*nq+1][1] = t4[3];
                ldsm_x4(t4, ad + 16384);
                bfl[2*nq][0] = t4[0]; bfl[2*nq][1] = t4[1];
                bfl[2*nq+1][0] = t4[2]; bfl[2*nq+1][1] = t4[3];
            }
#pragma unroll
            for (int mf = 0; mf < 2; mf++)
#pragma unroll
                for (int nf = 0; nf < 4; nf++) {
                    mma_bf16(accu[mf][nf], afh[mf], bfh[nf]);
                    mma_bf16(accu[mf][nf], afh[mf], bfl[nf]);
                    mma_bf16(accu[mf][nf], afl[mf], bfh[nf]);
                }
        }
    };

    // CORRECT 2-stage pipeline (fixes R16's uninitialized-read NaN)
    stage(0);
    for (int c = 0; c < KC; c++) {
        asm volatile("cp.async.wait_group 0;");
        __syncthreads();
        if (c + 1 < KC) stage(c + 1);
        compute(c & 1);
    }

    // epilogue: silu(g)*u -> bf16 hi/lo split
    __nv_bfloat16* act_hi = (__nv_bfloat16*)(g_scratch + act_hi_off);
    __nv_bfloat16* act_lo = (__nv_bfloat16*)(g_scratch + act_lo_off);
#pragma unroll
    for (int mf = 0; mf < 2; mf++) {
        int r0 = wm + mf * 16 + (lid >> 2);
#pragma unroll
        for (int hh = 0; hh < 2; hh++) {
            int rr = m0 + r0 + hh * 8;
            if (rr >= nrows) continue;
            size_t orow = (size_t)(seg + rr) * ND + (size_t)nb * 128;
#pragma unroll
            for (int nf = 0; nf < 4; nf++) {
                int col = wn + nf * 8 + (lid & 3) * 2;
                float a0 = silu(accg[mf][nf][hh*2+0]) * accu[mf][nf][hh*2+0];
                float a1 = silu(accg[mf][nf][hh*2+1]) * accu[mf][nf][hh*2+1];
                __nv_bfloat162 hp, lp;
                split_pair(a0, a1, hp, lp);
                *(__nv_bfloat162*)(act_hi + orow + col) = hp;
                *(__nv_bfloat162*)(act_lo + orow + col) = lp;
            }
        }
    }
}

// ---------------------------------------------------------------------------
// Down GEMM — exact R15 kernel (512 threads, CTA 128x128, warp 32x32,
// 3-stage pipeline with TWO pre-issued stages, one sync per chunk).
// AMODE: 0 plain rows, 2 slot rows. EMODE: 0 plain store, 1 scale+scatter.
// ---------------------------------------------------------------------------
constexpr int NSTAGE = 3;
constexpr int GSMEM_BYTES = NSTAGE * 65536;   // 192 KB

template <int KD, int ND, int AMODE, int EMODE>
__global__ void __launch_bounds__(GT)
mma_gemm(size_t a_hi_off, size_t a_lo_off,
         size_t w_hi_off, size_t w_lo_off,
         size_t out_off, float* ext_out) {
    constexpr int KC = KD / 64;
    constexpr int NT = ND / 128;
    extern __shared__ char smem[];
    uint32_t sb = smem_to_u32(smem);

    int e, seg, nrows;
    if (AMODE == 0) { e = 0; seg = 0; nrows = T_TOK; }
    else { e = blockIdx.z; seg = g_offsets[e]; nrows = g_offsets[e + 1] - seg; }
    int m0 = blockIdx.y * 128;
    if (m0 >= nrows) return;
    int nb = blockIdx.x;

    int tid = threadIdx.x, wid = tid >> 5, lid = tid & 31;

    const __nv_bfloat16* a_hi = (const __nv_bfloat16*)(g_scratch + a_hi_off);
    const __nv_bfloat16* a_lo = (const __nv_bfloat16*)(g_scratch + a_lo_off);
    int r = tid >> 2, q = tid & 3;
    int mrow = m0 + r;
    bool av = mrow < nrows;
    size_t arow;
    if (AMODE == 2) arow = (size_t)(seg + (av ? mrow : m0));
    else            arow = (size_t)(av ? mrow : m0);
    const char* ah0 = (const char*)(a_hi + arow * KD + q * 16);
    const char* al0 = (const char*)(a_lo + arow * KD + q * 16);
    uint32_t asw[2];
#pragma unroll
    for (int u = 0; u < 2; u++)
        asw[u] = swz32((uint32_t)(r * 128 + q * 32 + u * 16));

    size_t wtile = (size_t)(e * NT + nb) * KC;
    const char* bh0 = g_scratch + w_hi_off + wtile * 16384 + tid * 32;
    const char* bl0 = g_scratch + w_lo_off + wtile * 16384 + tid * 32;

    int wm = (wid & 3) * 32, wn = (wid >> 2) * 32;
    float acc[2][4][4];
#pragma unroll
    for (int a = 0; a < 2; a++)
#pragma unroll
        for (int b = 0; b < 4; b++)
#pragma unroll
            for (int c2 = 0; c2 < 4; c2++) acc[a][b][c2] = 0.f;

    auto stage = [&](int c) {
        uint32_t X = sb + (uint32_t)(c % NSTAGE) * 65536u;
        const char* ah = ah0 + (size_t)c * 128;
        const char* al = al0 + (size_t)c * 128;
        const char* bh = bh0 + (size_t)c * 16384;
        const char* bl = bl0 + (size_t)c * 16384;
#pragma unroll
        for (int u = 0; u < 2; u++) {
            cp16(X + asw[u],         ah + u * 16);
            cp16(X + 16384 + asw[u], al + u * 16);
        }
#pragma unroll
        for (int u = 0; u < 2; u++) {
            cp16(X + 32768 + tid * 32 + u * 16, bh + u * 16);
            cp16(X + 49152 + tid * 32 + u * 16, bl + u * 16);
        }
        asm volatile("cp.async.commit_group;");
    };

    auto compute = [&](int s) {
        uint32_t X = sb + (uint32_t)s * 65536u;
        int g = lid >> 3;
#pragma unroll
        for (int k16 = 0; k16 < 4; k16++) {
            int kb = k16 * 32;
            uint32_t afh[2][4], afl[2][4];
#pragma unroll
            for (int mf = 0; mf < 2; mf++) {
                int rr = wm + mf * 16 + (lid & 7) + (g & 1) * 8;
                int bb = kb + (g >> 1) * 16;
                uint32_t ad = X + swz32((uint32_t)(rr * 128 + bb));
                ldsm_x4(afh[mf], ad);
                ldsm_x4(afl[mf], ad + 16384);
            }
            uint32_t bfh[4][2], bfl[4][2];
#pragma unroll
            for (int nq = 0; nq < 2; nq++) {
                int rr = wn + nq * 16 + (lid & 7) + (g >> 1) * 8;
                int bb = kb + (g & 1) * 16;
                uint32_t ad = X + 32768 + swz32((uint32_t)(rr * 128 + bb));
                uint32_t t4[4];
                ldsm_x4(t4, ad);
                bfh[2*nq][0] = t4[0]; bfh[2*nq][1] = t4[1];
                bfh[2*nq+1][0] = t4[2]; bfh[2*nq+1][1] = t4[3];
                ldsm_x4(t4, ad + 16384);
                bfl[2*nq][0] = t4[0]; bfl[2*nq][1] = t4[1];
                bfl[2*nq+1][0] = t4[2]; bfl[2*nq+1][1] = t4[3];
            }
#pragma unroll
            for (int mf = 0; mf < 2; mf++)
#pragma unroll
                for (int nf = 0; nf < 4; nf++) {
                    mma_bf16(acc[mf][nf], afh[mf], bfh[nf]);
                    mma_bf16(acc[mf][nf], afh[mf], bfl[nf]);
                    mma_bf16(acc[mf][nf], afl[mf], bfh[nf]);
                }
        }
    };

    stage(0);
    stage(1);
    for (int c = 0; c < KC; c++) {
        if (c + 1 < KC) {
            asm volatile("cp.async.wait_group 1;");
        } else {
            asm volatile("cp.async.wait_group 0;");
        }
        __syncthreads();
        if (c + 2 < KC) stage(c + 2);
        compute(c % NSTAGE);
    }

#pragma unroll
    for (int mf = 0; mf < 2; mf++) {
        int r0 = m0 + wm + mf * 16 + (lid >> 2);
#pragma unroll
        for (int hh = 0; hh < 2; hh++) {
            int rr = r0 + hh * 8;
            if (rr - m0 >= 128 || rr >= nrows) continue;
            float wsc = 1.f;
            float* dst;
            if (EMODE == 1) {
                int slot = seg + rr;
                int tk = g_tk[slot];
                wsc = g_w[slot];
                dst = (float*)(g_scratch + O_PART) + (size_t)tk * HDIM + (size_t)nb * 128;
            } else {
                float* ob = ext_out ? ext_out : (float*)(g_scratch + out_off);
                dst = ob + (size_t)(seg + rr) * ND + (size_t)nb * 128;
            }
#pragma unroll
            for (int nf = 0; nf < 4; nf++) {
                int col = wn + nf * 8 + (lid & 3) * 2;
                float2 v;
                v.x = acc[mf][nf][hh * 2 + 0] * wsc;
                v.y = acc[mf][nf][hh * 2 + 1] * wsc;
                *(float2*)(dst + col) = v;
            }
        }
    }
}

// ---------------------------------------------------------------------------
// combine
// ---------------------------------------------------------------------------
__global__ void combine_kernel(float* __restrict__ out) {
    size_t i = (size_t)blockIdx.x * blockDim.x + threadIdx.x;
    size_t v = i * 4;
    int t = (int)(v / HDIM);
    int h = (int)(v % HDIM);
    const float* part = (const float*)(g_scratch + O_PART);
    float4 o = *(float4*)&out[v];
#pragma unroll
    for (int k = 0; k < TOPK; k++) {
        const float4 p = *(const float4*)&part[(size_t)(t * TOPK + k) * HDIM + h];
        o.x += p.x; o.y += p.y; o.z += p.z; o.w += p.w;
    }
    *(float4*)&out[v] = o;
}

// ---------------------------------------------------------------------------
// launch — idx 3 = FUSED shared gateup (ncu target)
// ---------------------------------------------------------------------------
extern "C" void kernel_launch(void* const* d_in, const int* in_sizes, int n_in,
                              void* d_out, int out_size) {
    const float* hidden      = (const float*)d_in[0];
    const float* gate_weight = (const float*)d_in[1];
    const float* bias        = (const float*)d_in[2];
    const float* gate_w      = (const float*)d_in[3];
    const float* up_w        = (const float*)d_in[4];
    const float* down_w      = (const float*)d_in[5];
    const float* sh_gate_w   = (const float*)d_in[6];
    const float* sh_up_w     = (const float*)d_in[7];
    const float* sh_down_w   = (const float*)d_in[8];
    float* out = (float*)d_out;

    cudaFuncSetAttribute(gu_mma<FMOE, 1>,
                         cudaFuncAttributeMaxDynamicSharedMemorySize, GU_SMEM);
    cudaFuncSetAttribute(gu_mma<FSH, 0>,
                         cudaFuncAttributeMaxDynamicSharedMemorySize, GU_SMEM);
    cudaFuncSetAttribute(mma_gemm<1024, 2048, 2, 1>,
                         cudaFuncAttributeMaxDynamicSharedMemorySize, GSMEM_BYTES);
    cudaFuncSetAttribute(mma_gemm<2048, 2048, 0, 0>,
                         cudaFuncAttributeMaxDynamicSharedMemorySize, GSMEM_BYTES);

    // idx 0: hidden split
    {
        int np = T_TOK * HDIM / 2;
        prep_split<<<(np + 255) / 256, 256>>>(hidden, O_HID_HI, O_HID_LO, np);
    }
    // idx 1-2: shared gate/up weights
    {
        int np = FSH * HDIM / 2;
        prep_weight<FSH, HDIM><<<(np + 255) / 256, 256>>>(sh_gate_w, O_WSG_HI, O_WSG_LO, np);
        prep_weight<FSH, HDIM><<<(np + 255) / 256, 256>>>(sh_up_w,   O_WSU_HI, O_WSU_LO, np);
    }

    // idx 3: FUSED shared gateup  <-- ncu profiles this
    gu_mma<FSH, 0><<<dim3(FSH / 128, T_TOK / 128, 1), GT, GU_SMEM>>>(
        O_HID_HI, O_HID_LO, O_WSG_HI, O_WSG_LO, O_WSU_HI, O_WSU_LO,
        O_SHA_HI, O_SHA_LO);
    // idx 4: shared down weights
    {
        int np = FSH * HDIM / 2;
        prep_weight<HDIM, FSH><<<(np + 255) / 256, 256>>>(sh_down_w, O_WSD_HI, O_WSD_LO, np);
    }
    // idx 5: shared down GEMM -> out
    mma_gemm<2048, 2048, 0, 0><<<dim3(HDIM / 128, T_TOK / 128, 1), GT, GSMEM_BYTES>>>(
        O_SHA_HI, O_SHA_LO, O_WSD_HI, O_WSD_LO, 0, out);

    // routed weight prep
    {
        int np = NEXP * FMOE * HDIM / 2;
        prep_weight<FMOE, HDIM><<<(np + 255) / 256, 256>>>(gate_w, O_WG_HI, O_WG_LO, np);
        prep_weight<FMOE, HDIM><<<(np + 255) / 256, 256>>>(up_w,   O_WU_HI, O_WU_LO, np);
    }
    {
        int np = NEXP * HDIM * FMOE / 2;
        prep_weight<HDIM, FMOE><<<(np + 255) / 256, 256>>>(down_w, O_WD_HI, O_WD_LO, np);
    }

    // routing
    zero_kernel<<<1, 32>>>();
    router_kernel<<<T_TOK, 512>>>(hidden, gate_weight, bias);
    offsets_kernel<<<1, 1>>>();
    dispatch_kernel<<<(T_TOK + 255) / 256, 256>>>();

    // routed experts: fused gateup, then down
    gu_mma<FMOE, 1><<<dim3(FMOE / 128, T_TOK / 128, NEXP), GT, GU_SMEM>>>(
        O_HID_HI, O_HID_LO, O_WG_HI, O_WG_LO, O_WU_HI, O_WU_LO,
        O_ACT_HI, O_ACT_LO);
    mma_gemm<1024, 2048, 2, 1><<<dim3(HDIM / 128, T_TOK / 128, NEXP), GT, GSMEM_BYTES>>>(
        O_ACT_HI, O_ACT_LO, O_WD_HI, O_WD_LO, 0, nullptr);

    // combine (routed partials on top of shared output already in `out`)
    combine_kernel<<<(T_TOK * HDIM / 4) / 256, 256>>>(out);
}